// round 1
// baseline (speedup 1.0000x reference)
#include <cuda_runtime.h>
#include <math.h>

#define DM 768
#define NH 12
#define DK 64
#define SMAX 4096

// Scratch (allocation-free): projected Q, K, V and attention context, [S, 768] row-major.
__device__ float g_Q[SMAX * DM];
__device__ float g_K[SMAX * DM];
__device__ float g_V[SMAX * DM];
__device__ float g_C[SMAX * DM];

// ---------------------------------------------------------------------------
// GEMM: C[M, 768] = A[M, 768] @ W[768, 768] + bias
// Block tile 64x64, BK=16, 256 threads, 4x4 micro-tile per thread.
// ---------------------------------------------------------------------------
__global__ __launch_bounds__(256) void gemm_bias_kernel(
    const float* __restrict__ A, const float* __restrict__ W,
    const float* __restrict__ bias, float* __restrict__ C, int M) {
    __shared__ float As[64][17];   // [m][kk], padded
    __shared__ float Ws[16][64];   // [kk][n]

    const int bn = blockIdx.x;           // 0..11  (N tile)
    const int bm = blockIdx.y;           // 0..M/64-1
    const int tid = threadIdx.x;
    const int tx = tid & 15;             // 0..15 -> n micro
    const int ty = tid >> 4;             // 0..15 -> m micro

    const int rowbase = bm * 64;
    const int colbase = bn * 64;

    float acc[4][4] = {};

    for (int k0 = 0; k0 < DM; k0 += 16) {
        // Load A tile: 64 rows x 16 k, coalesced along k (16 floats/row)
        #pragma unroll
        for (int i = tid; i < 64 * 16; i += 256) {
            int m = i >> 4, kk = i & 15;
            As[m][kk] = A[(size_t)(rowbase + m) * DM + k0 + kk];
        }
        // Load W tile: 16 k x 64 n, coalesced along n
        #pragma unroll
        for (int i = tid; i < 16 * 64; i += 256) {
            int kk = i >> 6, n = i & 63;
            Ws[kk][n] = W[(size_t)(k0 + kk) * DM + colbase + n];
        }
        __syncthreads();

        #pragma unroll
        for (int kk = 0; kk < 16; ++kk) {
            float a[4], w[4];
            #pragma unroll
            for (int i = 0; i < 4; ++i) a[i] = As[ty * 4 + i][kk];
            float4 wv = *reinterpret_cast<const float4*>(&Ws[kk][tx * 4]);
            w[0] = wv.x; w[1] = wv.y; w[2] = wv.z; w[3] = wv.w;
            #pragma unroll
            for (int i = 0; i < 4; ++i)
                #pragma unroll
                for (int j = 0; j < 4; ++j)
                    acc[i][j] = fmaf(a[i], w[j], acc[i][j]);
        }
        __syncthreads();
    }

    #pragma unroll
    for (int i = 0; i < 4; ++i) {
        int m = rowbase + ty * 4 + i;
        #pragma unroll
        for (int j = 0; j < 4; ++j) {
            int n = colbase + tx * 4 + j;
            C[(size_t)m * DM + n] = acc[i][j] + bias[n];
        }
    }
}

// ---------------------------------------------------------------------------
// Causal flash attention, fp32. One block = 64 query rows of one head.
// Online softmax. Tiles strictly above the diagonal are skipped.
// Shared: Qs/Ks/Vs/Ps each [64][65] (stride-65 => conflict-free row indexing).
// ---------------------------------------------------------------------------
__global__ __launch_bounds__(256) void attn_kernel(int S) {
    extern __shared__ float sm[];
    float (*Qs)[65] = reinterpret_cast<float (*)[65]>(sm);
    float (*Ks)[65] = reinterpret_cast<float (*)[65]>(sm + 64 * 65);
    float (*Vs)[65] = reinterpret_cast<float (*)[65]>(sm + 2 * 64 * 65);
    float (*Ps)[65] = reinterpret_cast<float (*)[65]>(sm + 3 * 64 * 65);

    const int qb = (gridDim.x - 1) - blockIdx.x;   // long blocks first
    const int h  = blockIdx.y;
    const int tid = threadIdx.x;
    const int tx = tid & 15;
    const int ty = tid >> 4;

    const float scale = 0.125f;  // 1/sqrt(64)

    // Load Q tile (scaled), coalesced along d
    #pragma unroll
    for (int i = tid; i < 64 * 64; i += 256) {
        int r = i >> 6, d = i & 63;
        Qs[r][d] = g_Q[(size_t)(qb * 64 + r) * DM + h * DK + d] * scale;
    }

    float mrow[4], lrow[4], o[4][4];
    #pragma unroll
    for (int i = 0; i < 4; ++i) {
        mrow[i] = -1e30f;
        lrow[i] = 0.0f;
        #pragma unroll
        for (int j = 0; j < 4; ++j) o[i][j] = 0.0f;
    }

    for (int t = 0; t <= qb; ++t) {
        // Load K and V tiles (coalesced along d). Sync protects prior-iter reads.
        __syncthreads();
        #pragma unroll
        for (int i = tid; i < 64 * 64; i += 256) {
            int r = i >> 6, d = i & 63;
            size_t g = (size_t)(t * 64 + r) * DM + h * DK + d;
            Ks[r][d] = g_K[g];
            Vs[r][d] = g_V[g];
        }
        __syncthreads();

        // S = Q K^T (scaled)
        float s[4][4] = {};
        #pragma unroll 8
        for (int d = 0; d < 64; ++d) {
            float qv[4], kv[4];
            #pragma unroll
            for (int i = 0; i < 4; ++i) qv[i] = Qs[ty * 4 + i][d];
            #pragma unroll
            for (int j = 0; j < 4; ++j) kv[j] = Ks[tx * 4 + j][d];
            #pragma unroll
            for (int i = 0; i < 4; ++i)
                #pragma unroll
                for (int j = 0; j < 4; ++j)
                    s[i][j] = fmaf(qv[i], kv[j], s[i][j]);
        }

        // Causal mask on the diagonal tile
        if (t == qb) {
            #pragma unroll
            for (int i = 0; i < 4; ++i) {
                int qr = qb * 64 + ty * 4 + i;
                #pragma unroll
                for (int j = 0; j < 4; ++j) {
                    int kc = t * 64 + tx * 4 + j;
                    if (kc > qr) s[i][j] = -1e30f;
                }
            }
        }

        // Online softmax per row (row = 16 lanes with same ty)
        #pragma unroll
        for (int i = 0; i < 4; ++i) {
            float rm = s[i][0];
            #pragma unroll
            for (int j = 1; j < 4; ++j) rm = fmaxf(rm, s[i][j]);
            #pragma unroll
            for (int off = 8; off > 0; off >>= 1)
                rm = fmaxf(rm, __shfl_xor_sync(0xffffffffu, rm, off, 16));

            float mn = fmaxf(mrow[i], rm);
            float corr = __expf(mrow[i] - mn);
            float rs = 0.0f;
            #pragma unroll
            for (int j = 0; j < 4; ++j) {
                float p = __expf(s[i][j] - mn);
                s[i][j] = p;
                rs += p;
            }
            #pragma unroll
            for (int off = 8; off > 0; off >>= 1)
                rs += __shfl_xor_sync(0xffffffffu, rs, off, 16);

            lrow[i] = lrow[i] * corr + rs;
            mrow[i] = mn;
            #pragma unroll
            for (int j = 0; j < 4; ++j) o[i][j] *= corr;
            #pragma unroll
            for (int j = 0; j < 4; ++j) Ps[ty * 4 + i][tx * 4 + j] = s[i][j];
        }
        __syncthreads();

        // O += P @ V
        #pragma unroll 8
        for (int k = 0; k < 64; ++k) {
            float pv[4], vv[4];
            #pragma unroll
            for (int i = 0; i < 4; ++i) pv[i] = Ps[ty * 4 + i][k];
            #pragma unroll
            for (int j = 0; j < 4; ++j) vv[j] = Vs[k][tx * 4 + j];
            #pragma unroll
            for (int i = 0; i < 4; ++i)
                #pragma unroll
                for (int j = 0; j < 4; ++j)
                    o[i][j] = fmaf(pv[i], vv[j], o[i][j]);
        }
    }

    // Normalize and write context
    #pragma unroll
    for (int i = 0; i < 4; ++i) {
        float inv = 1.0f / lrow[i];
        int qr = qb * 64 + ty * 4 + i;
        #pragma unroll
        for (int j = 0; j < 4; ++j) {
            g_C[(size_t)qr * DM + h * DK + tx * 4 + j] = o[i][j] * inv;
        }
    }
}

// ---------------------------------------------------------------------------
// Launch
// ---------------------------------------------------------------------------
extern "C" void kernel_launch(void* const* d_in, const int* in_sizes, int n_in,
                              void* d_out, int out_size) {
    const float* q  = (const float*)d_in[0];
    const float* k  = (const float*)d_in[1];
    const float* v  = (const float*)d_in[2];
    // d_in[3] = mask (tril, enforced analytically)
    const float* Wq = (const float*)d_in[4];
    const float* bq = (const float*)d_in[5];
    const float* Wk = (const float*)d_in[6];
    const float* bk = (const float*)d_in[7];
    const float* Wv = (const float*)d_in[8];
    const float* bv = (const float*)d_in[9];
    const float* Wo = (const float*)d_in[10];
    const float* bo = (const float*)d_in[11];
    float* out = (float*)d_out;

    const int S = in_sizes[0] / DM;   // 4096

    float *pQ, *pK, *pV, *pC;
    cudaGetSymbolAddress((void**)&pQ, g_Q);
    cudaGetSymbolAddress((void**)&pK, g_K);
    cudaGetSymbolAddress((void**)&pV, g_V);
    cudaGetSymbolAddress((void**)&pC, g_C);

    dim3 ggrid(DM / 64, S / 64);
    gemm_bias_kernel<<<ggrid, 256>>>(q, Wq, bq, pQ, S);
    gemm_bias_kernel<<<ggrid, 256>>>(k, Wk, bk, pK, S);
    gemm_bias_kernel<<<ggrid, 256>>>(v, Wv, bv, pV, S);

    const int smem_bytes = 4 * 64 * 65 * sizeof(float);  // 66,560 B
    cudaFuncSetAttribute(attn_kernel, cudaFuncAttributeMaxDynamicSharedMemorySize,
                         smem_bytes);
    attn_kernel<<<dim3(S / 64, NH), 256, smem_bytes>>>(S);

    gemm_bias_kernel<<<ggrid, 256>>>(pC, Wo, bo, out, S);
}

// round 4
// speedup vs baseline: 1.4281x; 1.4281x over previous
#include <cuda_runtime.h>
#include <math.h>
#include <stdint.h>

#define DM 768
#define NH 12
#define DK 64
#define SMAX 4096

// Scratch (allocation-free): projected Q, K, V and attention context, [S, 768] row-major.
__device__ float g_Q[SMAX * DM];
__device__ float g_K[SMAX * DM];
__device__ float g_V[SMAX * DM];
__device__ float g_C[SMAX * DM];

__device__ __forceinline__ uint32_t f2tf32(float f) {
    uint32_t r;
    asm("cvt.rna.tf32.f32 %0, %1;" : "=r"(r) : "f"(f));
    return r;
}

__device__ __forceinline__ void mma_tf32(float* d, const uint32_t* a, const uint32_t* b) {
    asm volatile(
        "mma.sync.aligned.m16n8k8.row.col.f32.tf32.tf32.f32 "
        "{%0,%1,%2,%3}, {%4,%5,%6,%7}, {%8,%9}, {%0,%1,%2,%3};"
        : "+f"(d[0]), "+f"(d[1]), "+f"(d[2]), "+f"(d[3])
        : "r"(a[0]), "r"(a[1]), "r"(a[2]), "r"(a[3]), "r"(b[0]), "r"(b[1]));
}

// ---------------------------------------------------------------------------
// Tensor-core GEMM via mma.sync (tf32): C[M,768] = A[M,768] @ W[768,768] + bias
// BM=128, BN=128, BK=16. 256 threads = 8 warps; warp tile 64x32
// (4 m-tiles of 16, 4 n-tiles of 8). Fragments hoisted per k8-step.
// ---------------------------------------------------------------------------
#define BM 128
#define BN 128
#define BK 16
#define AST 20    // As row stride (floats): banks 20g%32 = {0,20,8,28,16,4,24,12}
#define BST 136   // Bs row stride (floats): 136%32=8 -> b-frag reads hit 32 distinct banks

__global__ __launch_bounds__(256) void gemm_mma_kernel(
    const float* __restrict__ A, const float* __restrict__ W,
    const float* __restrict__ bias, float* __restrict__ C) {
    __shared__ uint32_t As[BM * AST];   // 10240 B
    __shared__ uint32_t Bs[BK * BST];   //  8704 B

    const int tid = threadIdx.x;
    const int wid = tid >> 5;
    const int lane = tid & 31;
    const int g = lane >> 2;        // groupID 0..7
    const int tg = lane & 3;        // threadID_in_group 0..3
    const int wm = (wid & 1) * 64;  // warp row offset in block
    const int wn = (wid >> 1) * 32; // warp col offset in block
    const int m0 = blockIdx.y * BM;
    const int n0 = blockIdx.x * BN;

    float acc[4][4][4] = {};  // [m-tile][n-tile][c0..c3]

    for (int k0 = 0; k0 < DM; k0 += BK) {
        __syncthreads();  // protect previous iteration's fragment reads

        // Load A tile 128x16 (float4, coalesced), convert to tf32.
        #pragma unroll
        for (int i = tid; i < BM * BK / 4; i += 256) {
            int r = i >> 2, cq = (i & 3) * 4;
            float4 v = *reinterpret_cast<const float4*>(
                &A[(size_t)(m0 + r) * DM + k0 + cq]);
            uint32_t* p = &As[r * AST + cq];
            p[0] = f2tf32(v.x); p[1] = f2tf32(v.y);
            p[2] = f2tf32(v.z); p[3] = f2tf32(v.w);
        }
        // Load B tile 16x128 = W[k0:k0+16][n0:n0+128] (float4, coalesced).
        #pragma unroll
        for (int i = tid; i < BK * BN / 4; i += 256) {
            int r = i >> 5, cq = (i & 31) * 4;
            float4 v = *reinterpret_cast<const float4*>(
                &W[(size_t)(k0 + r) * DM + n0 + cq]);
            uint32_t* p = &Bs[r * BST + cq];
            p[0] = f2tf32(v.x); p[1] = f2tf32(v.y);
            p[2] = f2tf32(v.z); p[3] = f2tf32(v.w);
        }
        __syncthreads();

        #pragma unroll
        for (int ks = 0; ks < BK; ks += 8) {
            uint32_t af[4][4], bf[4][2];
            #pragma unroll
            for (int mt = 0; mt < 4; ++mt) {
                int rb = wm + mt * 16;
                af[mt][0] = As[(rb + g) * AST + ks + tg];
                af[mt][1] = As[(rb + g + 8) * AST + ks + tg];
                af[mt][2] = As[(rb + g) * AST + ks + tg + 4];
                af[mt][3] = As[(rb + g + 8) * AST + ks + tg + 4];
            }
            #pragma unroll
            for (int nt = 0; nt < 4; ++nt) {
                int cb = wn + nt * 8;
                bf[nt][0] = Bs[(ks + tg) * BST + cb + g];
                bf[nt][1] = Bs[(ks + tg + 4) * BST + cb + g];
            }
            #pragma unroll
            for (int mt = 0; mt < 4; ++mt)
                #pragma unroll
                for (int nt = 0; nt < 4; ++nt)
                    mma_tf32(acc[mt][nt], af[mt], bf[nt]);
        }
    }

    // Epilogue: direct float2 stores with bias.
    #pragma unroll
    for (int mt = 0; mt < 4; ++mt) {
        int row = m0 + wm + mt * 16 + g;
        #pragma unroll
        for (int nt = 0; nt < 4; ++nt) {
            int col = n0 + wn + nt * 8 + tg * 2;
            float b0 = bias[col], b1 = bias[col + 1];
            float2 v0 = make_float2(acc[mt][nt][0] + b0, acc[mt][nt][1] + b1);
            float2 v1 = make_float2(acc[mt][nt][2] + b0, acc[mt][nt][3] + b1);
            *reinterpret_cast<float2*>(&C[(size_t)row * DM + col]) = v0;
            *reinterpret_cast<float2*>(&C[(size_t)(row + 8) * DM + col]) = v1;
        }
    }
}

// ---------------------------------------------------------------------------
// Causal flash attention, fp32 (unchanged from R1 — proven). One block = 64
// query rows of one head. Online softmax; tiles above the diagonal skipped.
// ---------------------------------------------------------------------------
__global__ __launch_bounds__(256) void attn_kernel(int S) {
    extern __shared__ float sm[];
    float (*Qs)[65] = reinterpret_cast<float (*)[65]>(sm);
    float (*Ks)[65] = reinterpret_cast<float (*)[65]>(sm + 64 * 65);
    float (*Vs)[65] = reinterpret_cast<float (*)[65]>(sm + 2 * 64 * 65);
    float (*Ps)[65] = reinterpret_cast<float (*)[65]>(sm + 3 * 64 * 65);

    const int qb = (gridDim.x - 1) - blockIdx.x;
    const int h  = blockIdx.y;
    const int tid = threadIdx.x;
    const int tx = tid & 15;
    const int ty = tid >> 4;

    const float scale = 0.125f;

    #pragma unroll
    for (int i = tid; i < 64 * 64; i += 256) {
        int r = i >> 6, d = i & 63;
        Qs[r][d] = g_Q[(size_t)(qb * 64 + r) * DM + h * DK + d] * scale;
    }

    float mrow[4], lrow[4], o[4][4];
    #pragma unroll
    for (int i = 0; i < 4; ++i) {
        mrow[i] = -1e30f;
        lrow[i] = 0.0f;
        #pragma unroll
        for (int j = 0; j < 4; ++j) o[i][j] = 0.0f;
    }

    for (int t = 0; t <= qb; ++t) {
        __syncthreads();
        #pragma unroll
        for (int i = tid; i < 64 * 64; i += 256) {
            int r = i >> 6, d = i & 63;
            size_t gg = (size_t)(t * 64 + r) * DM + h * DK + d;
            Ks[r][d] = g_K[gg];
            Vs[r][d] = g_V[gg];
        }
        __syncthreads();

        float s[4][4] = {};
        #pragma unroll 8
        for (int d = 0; d < 64; ++d) {
            float qv[4], kv[4];
            #pragma unroll
            for (int i = 0; i < 4; ++i) qv[i] = Qs[ty * 4 + i][d];
            #pragma unroll
            for (int j = 0; j < 4; ++j) kv[j] = Ks[tx * 4 + j][d];
            #pragma unroll
            for (int i = 0; i < 4; ++i)
                #pragma unroll
                for (int j = 0; j < 4; ++j)
                    s[i][j] = fmaf(qv[i], kv[j], s[i][j]);
        }

        if (t == qb) {
            #pragma unroll
            for (int i = 0; i < 4; ++i) {
                int qr = qb * 64 + ty * 4 + i;
                #pragma unroll
                for (int j = 0; j < 4; ++j) {
                    int kc = t * 64 + tx * 4 + j;
                    if (kc > qr) s[i][j] = -1e30f;
                }
            }
        }

        #pragma unroll
        for (int i = 0; i < 4; ++i) {
            float rm = s[i][0];
            #pragma unroll
            for (int j = 1; j < 4; ++j) rm = fmaxf(rm, s[i][j]);
            #pragma unroll
            for (int off = 8; off > 0; off >>= 1)
                rm = fmaxf(rm, __shfl_xor_sync(0xffffffffu, rm, off, 16));

            float mn = fmaxf(mrow[i], rm);
            float corr = __expf(mrow[i] - mn);
            float rs = 0.0f;
            #pragma unroll
            for (int j = 0; j < 4; ++j) {
                float p = __expf(s[i][j] - mn);
                s[i][j] = p;
                rs += p;
            }
            #pragma unroll
            for (int off = 8; off > 0; off >>= 1)
                rs += __shfl_xor_sync(0xffffffffu, rs, off, 16);

            lrow[i] = lrow[i] * corr + rs;
            mrow[i] = mn;
            #pragma unroll
            for (int j = 0; j < 4; ++j) o[i][j] *= corr;
            #pragma unroll
            for (int j = 0; j < 4; ++j) Ps[ty * 4 + i][tx * 4 + j] = s[i][j];
        }
        __syncthreads();

        #pragma unroll 8
        for (int k = 0; k < 64; ++k) {
            float pv[4], vv[4];
            #pragma unroll
            for (int i = 0; i < 4; ++i) pv[i] = Ps[ty * 4 + i][k];
            #pragma unroll
            for (int j = 0; j < 4; ++j) vv[j] = Vs[k][tx * 4 + j];
            #pragma unroll
            for (int i = 0; i < 4; ++i)
                #pragma unroll
                for (int j = 0; j < 4; ++j)
                    o[i][j] = fmaf(pv[i], vv[j], o[i][j]);
        }
    }

    #pragma unroll
    for (int i = 0; i < 4; ++i) {
        float inv = 1.0f / lrow[i];
        int qr = qb * 64 + ty * 4 + i;
        #pragma unroll
        for (int j = 0; j < 4; ++j) {
            g_C[(size_t)qr * DM + h * DK + tx * 4 + j] = o[i][j] * inv;
        }
    }
}

// ---------------------------------------------------------------------------
// Launch
// ---------------------------------------------------------------------------
extern "C" void kernel_launch(void* const* d_in, const int* in_sizes, int n_in,
                              void* d_out, int out_size) {
    const float* q  = (const float*)d_in[0];
    const float* k  = (const float*)d_in[1];
    const float* v  = (const float*)d_in[2];
    // d_in[3] = mask (tril, enforced analytically)
    const float* Wq = (const float*)d_in[4];
    const float* bq = (const float*)d_in[5];
    const float* Wk = (const float*)d_in[6];
    const float* bk = (const float*)d_in[7];
    const float* Wv = (const float*)d_in[8];
    const float* bv = (const float*)d_in[9];
    const float* Wo = (const float*)d_in[10];
    const float* bo = (const float*)d_in[11];
    float* out = (float*)d_out;

    const int S = in_sizes[0] / DM;   // 4096

    float *pQ, *pK, *pV, *pC;
    cudaGetSymbolAddress((void**)&pQ, g_Q);
    cudaGetSymbolAddress((void**)&pK, g_K);
    cudaGetSymbolAddress((void**)&pV, g_V);
    cudaGetSymbolAddress((void**)&pC, g_C);

    dim3 ggrid(DM / BN, S / BM);   // (6, 32)
    gemm_mma_kernel<<<ggrid, 256>>>(q, Wq, bq, pQ);
    gemm_mma_kernel<<<ggrid, 256>>>(k, Wk, bk, pK);
    gemm_mma_kernel<<<ggrid, 256>>>(v, Wv, bv, pV);

    const int smem_bytes = 4 * 64 * 65 * sizeof(float);  // 66,560 B
    cudaFuncSetAttribute(attn_kernel, cudaFuncAttributeMaxDynamicSharedMemorySize,
                         smem_bytes);
    attn_kernel<<<dim3(S / 64, NH), 256, smem_bytes>>>(S);

    gemm_mma_kernel<<<ggrid, 256>>>(pC, Wo, bo, out);
}

// round 5
// speedup vs baseline: 1.7914x; 1.2544x over previous
#include <cuda_runtime.h>
#include <math.h>
#include <stdint.h>

#define DM 768
#define NH 12
#define DK 64
#define SMAX 4096

__device__ float g_Q[SMAX * DM];
__device__ float g_K[SMAX * DM];
__device__ float g_V[SMAX * DM];
__device__ float g_C[SMAX * DM];

__device__ __forceinline__ uint32_t f2tf32(float f) {
    uint32_t r;
    asm("cvt.rna.tf32.f32 %0, %1;" : "=r"(r) : "f"(f));
    return r;
}

__device__ __forceinline__ void mma_tf32(float* d, const uint32_t* a, const uint32_t* b) {
    asm volatile(
        "mma.sync.aligned.m16n8k8.row.col.f32.tf32.tf32.f32 "
        "{%0,%1,%2,%3}, {%4,%5,%6,%7}, {%8,%9}, {%0,%1,%2,%3};"
        : "+f"(d[0]), "+f"(d[1]), "+f"(d[2]), "+f"(d[3])
        : "r"(a[0]), "r"(a[1]), "r"(a[2]), "r"(a[3]), "r"(b[0]), "r"(b[1]));
}

// ---------------------------------------------------------------------------
// GEMM via mma.sync, 3x-tf32 split (hi*hi + hi*lo + lo*hi): near-fp32 accuracy.
// C[M,768] = A[M,768] @ W[768,768] + bias. BM=128, BN=128, BK=16, 256 thr.
// ---------------------------------------------------------------------------
#define BM 128
#define BN 128
#define BK 16
#define AST 20
#define BST 136

__global__ __launch_bounds__(256) void gemm_mma_kernel(
    const float* __restrict__ A, const float* __restrict__ W,
    const float* __restrict__ bias, float* __restrict__ C) {
    __shared__ uint32_t AsH[BM * AST], AsL[BM * AST];
    __shared__ uint32_t BsH[BK * BST], BsL[BK * BST];

    const int tid = threadIdx.x;
    const int wid = tid >> 5;
    const int lane = tid & 31;
    const int g = lane >> 2;
    const int tg = lane & 3;
    const int wm = (wid & 1) * 64;
    const int wn = (wid >> 1) * 32;
    const int m0 = blockIdx.y * BM;
    const int n0 = blockIdx.x * BN;

    float acc[4][4][4] = {};

    for (int k0 = 0; k0 < DM; k0 += BK) {
        __syncthreads();

        #pragma unroll
        for (int i = tid; i < BM * BK / 4; i += 256) {
            int r = i >> 2, cq = (i & 3) * 4;
            float4 v = *reinterpret_cast<const float4*>(
                &A[(size_t)(m0 + r) * DM + k0 + cq]);
            uint32_t* ph = &AsH[r * AST + cq];
            uint32_t* pl = &AsL[r * AST + cq];
            float f[4] = {v.x, v.y, v.z, v.w};
            #pragma unroll
            for (int j = 0; j < 4; ++j) {
                uint32_t hi = f2tf32(f[j]);
                ph[j] = hi;
                pl[j] = f2tf32(f[j] - __uint_as_float(hi));
            }
        }
        #pragma unroll
        for (int i = tid; i < BK * BN / 4; i += 256) {
            int r = i >> 5, cq = (i & 31) * 4;
            float4 v = *reinterpret_cast<const float4*>(
                &W[(size_t)(k0 + r) * DM + n0 + cq]);
            uint32_t* ph = &BsH[r * BST + cq];
            uint32_t* pl = &BsL[r * BST + cq];
            float f[4] = {v.x, v.y, v.z, v.w};
            #pragma unroll
            for (int j = 0; j < 4; ++j) {
                uint32_t hi = f2tf32(f[j]);
                ph[j] = hi;
                pl[j] = f2tf32(f[j] - __uint_as_float(hi));
            }
        }
        __syncthreads();

        #pragma unroll
        for (int ks = 0; ks < BK; ks += 8) {
            uint32_t afh[4][4], bfh[4][2], bfl[4][2];
            #pragma unroll
            for (int mt = 0; mt < 4; ++mt) {
                int rb = wm + mt * 16;
                afh[mt][0] = AsH[(rb + g) * AST + ks + tg];
                afh[mt][1] = AsH[(rb + g + 8) * AST + ks + tg];
                afh[mt][2] = AsH[(rb + g) * AST + ks + tg + 4];
                afh[mt][3] = AsH[(rb + g + 8) * AST + ks + tg + 4];
            }
            #pragma unroll
            for (int nt = 0; nt < 4; ++nt) {
                int cb = wn + nt * 8;
                bfh[nt][0] = BsH[(ks + tg) * BST + cb + g];
                bfh[nt][1] = BsH[(ks + tg + 4) * BST + cb + g];
                bfl[nt][0] = BsL[(ks + tg) * BST + cb + g];
                bfl[nt][1] = BsL[(ks + tg + 4) * BST + cb + g];
            }
            // hi*lo
            #pragma unroll
            for (int mt = 0; mt < 4; ++mt)
                #pragma unroll
                for (int nt = 0; nt < 4; ++nt)
                    mma_tf32(acc[mt][nt], afh[mt], bfl[nt]);
            // lo*hi (overwrite A frags with lo parts)
            uint32_t afl[4][4];
            #pragma unroll
            for (int mt = 0; mt < 4; ++mt) {
                int rb = wm + mt * 16;
                afl[mt][0] = AsL[(rb + g) * AST + ks + tg];
                afl[mt][1] = AsL[(rb + g + 8) * AST + ks + tg];
                afl[mt][2] = AsL[(rb + g) * AST + ks + tg + 4];
                afl[mt][3] = AsL[(rb + g + 8) * AST + ks + tg + 4];
            }
            #pragma unroll
            for (int mt = 0; mt < 4; ++mt)
                #pragma unroll
                for (int nt = 0; nt < 4; ++nt)
                    mma_tf32(acc[mt][nt], afl[mt], bfh[nt]);
            // hi*hi
            #pragma unroll
            for (int mt = 0; mt < 4; ++mt)
                #pragma unroll
                for (int nt = 0; nt < 4; ++nt)
                    mma_tf32(acc[mt][nt], afh[mt], bfh[nt]);
        }
    }

    #pragma unroll
    for (int mt = 0; mt < 4; ++mt) {
        int row = m0 + wm + mt * 16 + g;
        #pragma unroll
        for (int nt = 0; nt < 4; ++nt) {
            int col = n0 + wn + nt * 8 + tg * 2;
            float b0 = bias[col], b1 = bias[col + 1];
            float2 v0 = make_float2(acc[mt][nt][0] + b0, acc[mt][nt][1] + b1);
            float2 v1 = make_float2(acc[mt][nt][2] + b0, acc[mt][nt][3] + b1);
            *reinterpret_cast<float2*>(&C[(size_t)row * DM + col]) = v0;
            *reinterpret_cast<float2*>(&C[(size_t)(row + 8) * DM + col]) = v1;
        }
    }
}

// ---------------------------------------------------------------------------
// Tensorized causal flash attention (tf32 mma.sync).
// Block = 128 q rows of one head; 8 warps x 16 rows. KV tiles of 64.
// Q fragments live in registers; K/V/P staged in smem with conflict-free
// strides. Online softmax on mma accumulator fragments.
// ---------------------------------------------------------------------------
#define KST 68   // Ks row stride: banks (4g+tg) distinct for B-frag gather
#define VST 72   // Vs row stride: banks (8tg+g) distinct for B-frag gather
#define PST 68   // Ps row stride: banks (4g+tg) distinct for A-frag gather
#define ATTN_SMEM ((64 * KST + 64 * VST + 128 * PST) * 4)

__global__ __launch_bounds__(256) void attn_mma_kernel() {
    extern __shared__ uint32_t sm[];
    uint32_t* Ks = sm;                 // [64][KST]
    uint32_t* Vs = Ks + 64 * KST;      // [64][VST]
    uint32_t* Ps = Vs + 64 * VST;      // [128][PST] (Q staging, then P)

    const int qb = (gridDim.x - 1) - blockIdx.x;
    const int h = blockIdx.y;
    const int tid = threadIdx.x;
    const int w = tid >> 5;
    const int lane = tid & 31;
    const int g = lane >> 2;
    const int tg = lane & 3;
    const int r0g = qb * 128 + w * 16 + g;   // global row of this thread's row0

    // Stage Q (scaled, tf32) into Ps, then gather A-fragments into registers.
    #pragma unroll 2
    for (int i = tid; i < 128 * 16; i += 256) {
        int r = i >> 4, cq = (i & 15) * 4;
        float4 v = *reinterpret_cast<const float4*>(
            &g_Q[(size_t)(qb * 128 + r) * DM + h * DK + cq]);
        uint32_t* p = &Ps[r * PST + cq];
        p[0] = f2tf32(v.x * 0.125f);
        p[1] = f2tf32(v.y * 0.125f);
        p[2] = f2tf32(v.z * 0.125f);
        p[3] = f2tf32(v.w * 0.125f);
    }
    __syncthreads();

    uint32_t qa[8][4];
    #pragma unroll
    for (int kc = 0; kc < 8; ++kc) {
        qa[kc][0] = Ps[(w * 16 + g) * PST + kc * 8 + tg];
        qa[kc][1] = Ps[(w * 16 + g + 8) * PST + kc * 8 + tg];
        qa[kc][2] = Ps[(w * 16 + g) * PST + kc * 8 + tg + 4];
        qa[kc][3] = Ps[(w * 16 + g + 8) * PST + kc * 8 + tg + 4];
    }

    float m0 = -1e30f, m1 = -1e30f, l0 = 0.0f, l1 = 0.0f;
    float o[8][4] = {};

    const int ntiles = 2 * qb + 2;
    for (int t = 0; t < ntiles; ++t) {
        __syncthreads();   // protect Ks/Vs/Ps reads of previous iteration

        // Load K and V tiles [64 keys][64 dk], convert tf32.
        #pragma unroll 2
        for (int i = tid; i < 64 * 16; i += 256) {
            int r = i >> 4, cq = (i & 15) * 4;
            size_t gk = (size_t)(t * 64 + r) * DM + h * DK + cq;
            float4 kv = *reinterpret_cast<const float4*>(&g_K[gk]);
            float4 vv = *reinterpret_cast<const float4*>(&g_V[gk]);
            uint32_t* pk = &Ks[r * KST + cq];
            pk[0] = f2tf32(kv.x); pk[1] = f2tf32(kv.y);
            pk[2] = f2tf32(kv.z); pk[3] = f2tf32(kv.w);
            uint32_t* pv = &Vs[r * VST + cq];
            pv[0] = f2tf32(vv.x); pv[1] = f2tf32(vv.y);
            pv[2] = f2tf32(vv.z); pv[3] = f2tf32(vv.w);
        }
        __syncthreads();

        const bool warp_active = (t * 64 <= qb * 128 + w * 16 + 15);

        if (warp_active) {
            // S = Q K^T : 8 n-tiles x 8 k-steps of m16n8k8
            float sa[8][4] = {};
            #pragma unroll
            for (int kc = 0; kc < 8; ++kc) {
                uint32_t bf[8][2];
                #pragma unroll
                for (int nt = 0; nt < 8; ++nt) {
                    bf[nt][0] = Ks[(nt * 8 + g) * KST + kc * 8 + tg];
                    bf[nt][1] = Ks[(nt * 8 + g) * KST + kc * 8 + tg + 4];
                }
                #pragma unroll
                for (int nt = 0; nt < 8; ++nt)
                    mma_tf32(sa[nt], qa[kc], bf[nt]);
            }

            // Causal mask (only diagonal-overlapping tiles)
            if (t >= 2 * qb) {
                #pragma unroll
                for (int nt = 0; nt < 8; ++nt) {
                    int c0 = t * 64 + nt * 8 + 2 * tg;
                    if (c0 > r0g)         sa[nt][0] = -1e30f;
                    if (c0 + 1 > r0g)     sa[nt][1] = -1e30f;
                    if (c0 > r0g + 8)     sa[nt][2] = -1e30f;
                    if (c0 + 1 > r0g + 8) sa[nt][3] = -1e30f;
                }
            }

            // Online softmax (rows g and g+8; reduce over the 4-lane quad)
            float smax0 = -1e30f, smax1 = -1e30f;
            #pragma unroll
            for (int nt = 0; nt < 8; ++nt) {
                smax0 = fmaxf(smax0, fmaxf(sa[nt][0], sa[nt][1]));
                smax1 = fmaxf(smax1, fmaxf(sa[nt][2], sa[nt][3]));
            }
            smax0 = fmaxf(smax0, __shfl_xor_sync(0xffffffffu, smax0, 1));
            smax0 = fmaxf(smax0, __shfl_xor_sync(0xffffffffu, smax0, 2));
            smax1 = fmaxf(smax1, __shfl_xor_sync(0xffffffffu, smax1, 1));
            smax1 = fmaxf(smax1, __shfl_xor_sync(0xffffffffu, smax1, 2));

            float mn0 = fmaxf(m0, smax0);
            float mn1 = fmaxf(m1, smax1);
            float corr0 = __expf(m0 - mn0);
            float corr1 = __expf(m1 - mn1);
            float rs0 = 0.0f, rs1 = 0.0f;
            #pragma unroll
            for (int nt = 0; nt < 8; ++nt) {
                sa[nt][0] = __expf(sa[nt][0] - mn0);
                sa[nt][1] = __expf(sa[nt][1] - mn0);
                sa[nt][2] = __expf(sa[nt][2] - mn1);
                sa[nt][3] = __expf(sa[nt][3] - mn1);
                rs0 += sa[nt][0] + sa[nt][1];
                rs1 += sa[nt][2] + sa[nt][3];
            }
            rs0 += __shfl_xor_sync(0xffffffffu, rs0, 1);
            rs0 += __shfl_xor_sync(0xffffffffu, rs0, 2);
            rs1 += __shfl_xor_sync(0xffffffffu, rs1, 1);
            rs1 += __shfl_xor_sync(0xffffffffu, rs1, 2);

            l0 = l0 * corr0 + rs0;  m0 = mn0;
            l1 = l1 * corr1 + rs1;  m1 = mn1;
            #pragma unroll
            for (int nt = 0; nt < 8; ++nt) {
                o[nt][0] *= corr0;  o[nt][1] *= corr0;
                o[nt][2] *= corr1;  o[nt][3] *= corr1;
            }

            // Store P (tf32) to Ps for A-fragment re-gather
            #pragma unroll
            for (int nt = 0; nt < 8; ++nt) {
                int c = nt * 8 + 2 * tg;
                uint2 p0 = make_uint2(f2tf32(sa[nt][0]), f2tf32(sa[nt][1]));
                uint2 p1 = make_uint2(f2tf32(sa[nt][2]), f2tf32(sa[nt][3]));
                *reinterpret_cast<uint2*>(&Ps[(w * 16 + g) * PST + c]) = p0;
                *reinterpret_cast<uint2*>(&Ps[(w * 16 + g + 8) * PST + c]) = p1;
            }
        }
        __syncthreads();

        if (warp_active) {
            // O += P V : k-dim = 64 keys
            #pragma unroll
            for (int kc = 0; kc < 8; ++kc) {
                uint32_t pa[4];
                pa[0] = Ps[(w * 16 + g) * PST + kc * 8 + tg];
                pa[1] = Ps[(w * 16 + g + 8) * PST + kc * 8 + tg];
                pa[2] = Ps[(w * 16 + g) * PST + kc * 8 + tg + 4];
                pa[3] = Ps[(w * 16 + g + 8) * PST + kc * 8 + tg + 4];
                uint32_t bf[8][2];
                #pragma unroll
                for (int nt = 0; nt < 8; ++nt) {
                    bf[nt][0] = Vs[(kc * 8 + tg) * VST + nt * 8 + g];
                    bf[nt][1] = Vs[(kc * 8 + tg + 4) * VST + nt * 8 + g];
                }
                #pragma unroll
                for (int nt = 0; nt < 8; ++nt)
                    mma_tf32(o[nt], pa, bf[nt]);
            }
        }
    }

    // Epilogue: normalize, write context
    float inv0 = 1.0f / l0;
    float inv1 = 1.0f / l1;
    #pragma unroll
    for (int nt = 0; nt < 8; ++nt) {
        int col = h * DK + nt * 8 + 2 * tg;
        float2 v0 = make_float2(o[nt][0] * inv0, o[nt][1] * inv0);
        float2 v1 = make_float2(o[nt][2] * inv1, o[nt][3] * inv1);
        *reinterpret_cast<float2*>(&g_C[(size_t)r0g * DM + col]) = v0;
        *reinterpret_cast<float2*>(&g_C[(size_t)(r0g + 8) * DM + col]) = v1;
    }
}

// ---------------------------------------------------------------------------
// Launch
// ---------------------------------------------------------------------------
extern "C" void kernel_launch(void* const* d_in, const int* in_sizes, int n_in,
                              void* d_out, int out_size) {
    const float* q  = (const float*)d_in[0];
    const float* k  = (const float*)d_in[1];
    const float* v  = (const float*)d_in[2];
    // d_in[3] = mask (tril, enforced analytically)
    const float* Wq = (const float*)d_in[4];
    const float* bq = (const float*)d_in[5];
    const float* Wk = (const float*)d_in[6];
    const float* bk = (const float*)d_in[7];
    const float* Wv = (const float*)d_in[8];
    const float* bv = (const float*)d_in[9];
    const float* Wo = (const float*)d_in[10];
    const float* bo = (const float*)d_in[11];
    float* out = (float*)d_out;

    const int S = in_sizes[0] / DM;   // 4096

    float *pQ, *pK, *pV, *pC;
    cudaGetSymbolAddress((void**)&pQ, g_Q);
    cudaGetSymbolAddress((void**)&pK, g_K);
    cudaGetSymbolAddress((void**)&pV, g_V);
    cudaGetSymbolAddress((void**)&pC, g_C);

    dim3 ggrid(DM / BN, S / BM);   // (6, 32)
    gemm_mma_kernel<<<ggrid, 256>>>(q, Wq, bq, pQ);
    gemm_mma_kernel<<<ggrid, 256>>>(k, Wk, bk, pK);
    gemm_mma_kernel<<<ggrid, 256>>>(v, Wv, bv, pV);

    cudaFuncSetAttribute(attn_mma_kernel,
                         cudaFuncAttributeMaxDynamicSharedMemorySize, ATTN_SMEM);
    attn_mma_kernel<<<dim3(S / 128, NH), 256, ATTN_SMEM>>>();

    gemm_mma_kernel<<<ggrid, 256>>>(pC, Wo, bo, out);
}

// round 6
// speedup vs baseline: 2.6634x; 1.4868x over previous
#include <cuda_runtime.h>
#include <math.h>
#include <stdint.h>

#define DM 768
#define NH 12
#define DK 64
#define SMAX 4096

__device__ float g_Q[SMAX * DM];
__device__ float g_K[SMAX * DM];
__device__ float g_V[SMAX * DM];
__device__ float g_C[SMAX * DM];

__device__ __forceinline__ uint32_t f2tf32(float f) {
    uint32_t r;
    asm("cvt.rna.tf32.f32 %0, %1;" : "=r"(r) : "f"(f));
    return r;
}

__device__ __forceinline__ uint32_t smem_u32(const void* p) {
    uint32_t a;
    asm("{ .reg .u64 t; cvta.to.shared.u64 t, %1; cvt.u32.u64 %0, t; }"
        : "=r"(a) : "l"(p));
    return a;
}

__device__ __forceinline__ void cp_async16(uint32_t smem_addr, const void* gptr) {
    asm volatile("cp.async.ca.shared.global [%0], [%1], 16;"
                 :: "r"(smem_addr), "l"(gptr));
}
__device__ __forceinline__ void cp_commit() {
    asm volatile("cp.async.commit_group;");
}
template <int N>
__device__ __forceinline__ void cp_wait() {
    asm volatile("cp.async.wait_group %0;" :: "n"(N));
}

__device__ __forceinline__ void mma_tf32(float* d, const uint32_t* a, const uint32_t* b) {
    asm volatile(
        "mma.sync.aligned.m16n8k8.row.col.f32.tf32.tf32.f32 "
        "{%0,%1,%2,%3}, {%4,%5,%6,%7}, {%8,%9}, {%0,%1,%2,%3};"
        : "+f"(d[0]), "+f"(d[1]), "+f"(d[2]), "+f"(d[3])
        : "r"(a[0]), "r"(a[1]), "r"(a[2]), "r"(a[3]), "r"(b[0]), "r"(b[1]));
}

// ---------------------------------------------------------------------------
// GEMM core: C[M,768] = A[M,768] @ W[768,768] + bias.
// 2x-tf32 (W split hi/lo, A rounded once): rel err ~ half of plain tf32.
// BM=128, BN=128, BK=16; 2-stage cp.async double buffer; 256 threads.
// ---------------------------------------------------------------------------
#define BM 128
#define BN 128
#define BK 16
#define AST 20    // A smem stride: banks (20g+tg)%32 all distinct
#define BST 136   // B smem stride: banks (8tg+g) all distinct

__device__ __forceinline__ void gemm_core(
    const float* __restrict__ A, const float* __restrict__ W,
    const float* __restrict__ bias, float* __restrict__ C,
    int m0, int n0) {
    __shared__ float AsF[2][BM * AST];
    __shared__ float BsF[2][BK * BST];

    const int tid = threadIdx.x;
    const int wid = tid >> 5;
    const int lane = tid & 31;
    const int g = lane >> 2;
    const int tg = lane & 3;
    const int wm = (wid & 1) * 64;
    const int wn = (wid >> 1) * 32;

    const uint32_t sA0 = smem_u32(AsF[0]);
    const uint32_t sA1 = smem_u32(AsF[1]);
    const uint32_t sB0 = smem_u32(BsF[0]);
    const uint32_t sB1 = smem_u32(BsF[1]);

    // Per-thread load slots (2 A-chunks + 2 B-chunks of 16B each)
    const int ar0 = (tid * 2) >> 2, ac0 = ((tid * 2) & 3) * 4;
    const int ar1 = (tid * 2 + 1) >> 2, ac1 = ((tid * 2 + 1) & 3) * 4;
    const int br0 = (tid * 2) >> 6, bc0 = ((tid * 2) & 63) * 2;   // 16x128: i>>6? 
    // NOTE: B tile has 16 rows x 128 cols -> 512 float4 slots: r = i>>5, c=(i&31)*4
    const int brr0 = (tid * 2) >> 5, bcc0 = ((tid * 2) & 31) * 4;
    const int brr1 = (tid * 2 + 1) >> 5, bcc1 = ((tid * 2 + 1) & 31) * 4;
    (void)br0; (void)bc0;

    float acc[4][4][4] = {};

    auto load_tile = [&](int ki, int st) {
        uint32_t sa = st ? sA1 : sA0;
        uint32_t sb = st ? sB1 : sB0;
        const int k0 = ki * BK;
        cp_async16(sa + (ar0 * AST + ac0) * 4, &A[(size_t)(m0 + ar0) * DM + k0 + ac0]);
        cp_async16(sa + (ar1 * AST + ac1) * 4, &A[(size_t)(m0 + ar1) * DM + k0 + ac1]);
        cp_async16(sb + (brr0 * BST + bcc0) * 4, &W[(size_t)(k0 + brr0) * DM + n0 + bcc0]);
        cp_async16(sb + (brr1 * BST + bcc1) * 4, &W[(size_t)(k0 + brr1) * DM + n0 + bcc1]);
        cp_commit();
    };

    load_tile(0, 0);

    const int NIT = DM / BK;  // 48
    for (int ki = 0; ki < NIT; ++ki) {
        const int st = ki & 1;
        if (ki + 1 < NIT) {
            load_tile(ki + 1, st ^ 1);
            cp_wait<1>();
        } else {
            cp_wait<0>();
        }
        __syncthreads();

        const float* Af = AsF[st];
        const float* Bf = BsF[st];

        #pragma unroll
        for (int ks = 0; ks < BK; ks += 8) {
            uint32_t af[4][4];
            uint32_t bfh[4][2], bfl[4][2];
            #pragma unroll
            for (int mt = 0; mt < 4; ++mt) {
                int rb = wm + mt * 16;
                af[mt][0] = f2tf32(Af[(rb + g) * AST + ks + tg]);
                af[mt][1] = f2tf32(Af[(rb + g + 8) * AST + ks + tg]);
                af[mt][2] = f2tf32(Af[(rb + g) * AST + ks + tg + 4]);
                af[mt][3] = f2tf32(Af[(rb + g + 8) * AST + ks + tg + 4]);
            }
            #pragma unroll
            for (int nt = 0; nt < 4; ++nt) {
                int cb = wn + nt * 8;
                float b0 = Bf[(ks + tg) * BST + cb + g];
                float b1 = Bf[(ks + tg + 4) * BST + cb + g];
                bfh[nt][0] = f2tf32(b0);
                bfh[nt][1] = f2tf32(b1);
                bfl[nt][0] = f2tf32(b0 - __uint_as_float(bfh[nt][0]));
                bfl[nt][1] = f2tf32(b1 - __uint_as_float(bfh[nt][1]));
            }
            #pragma unroll
            for (int mt = 0; mt < 4; ++mt)
                #pragma unroll
                for (int nt = 0; nt < 4; ++nt)
                    mma_tf32(acc[mt][nt], af[mt], bfl[nt]);
            #pragma unroll
            for (int mt = 0; mt < 4; ++mt)
                #pragma unroll
                for (int nt = 0; nt < 4; ++nt)
                    mma_tf32(acc[mt][nt], af[mt], bfh[nt]);
        }
        __syncthreads();
    }

    #pragma unroll
    for (int mt = 0; mt < 4; ++mt) {
        int row = m0 + wm + mt * 16 + g;
        #pragma unroll
        for (int nt = 0; nt < 4; ++nt) {
            int col = n0 + wn + nt * 8 + tg * 2;
            float b0 = bias[col], b1 = bias[col + 1];
            float2 v0 = make_float2(acc[mt][nt][0] + b0, acc[mt][nt][1] + b1);
            float2 v1 = make_float2(acc[mt][nt][2] + b0, acc[mt][nt][3] + b1);
            *reinterpret_cast<float2*>(&C[(size_t)row * DM + col]) = v0;
            *reinterpret_cast<float2*>(&C[(size_t)(row + 8) * DM + col]) = v1;
        }
    }
}

// Fused QKV projection: blockIdx.z picks which of the 3 GEMMs.
__global__ __launch_bounds__(256) void gemm_qkv_kernel(
    const float* A0, const float* A1, const float* A2,
    const float* W0, const float* W1, const float* W2,
    const float* b0, const float* b1, const float* b2,
    float* C0, float* C1, float* C2) {
    const int z = blockIdx.z;
    const float* A = (z == 0) ? A0 : (z == 1) ? A1 : A2;
    const float* W = (z == 0) ? W0 : (z == 1) ? W1 : W2;
    const float* b = (z == 0) ? b0 : (z == 1) ? b1 : b2;
    float* C = (z == 0) ? C0 : (z == 1) ? C1 : C2;
    gemm_core(A, W, b, C, blockIdx.y * BM, blockIdx.x * BN);
}

__global__ __launch_bounds__(256) void gemm_single_kernel(
    const float* __restrict__ A, const float* __restrict__ W,
    const float* __restrict__ bias, float* __restrict__ C) {
    gemm_core(A, W, bias, C, blockIdx.y * BM, blockIdx.x * BN);
}

// ---------------------------------------------------------------------------
// Tensorized causal flash attention (tf32 mma.sync) with cp.async
// double-buffered K/V tiles. Block = 128 q rows of one head; KV tiles of 64.
// ---------------------------------------------------------------------------
#define KST 68
#define VST 72
#define PST 68
// smem floats: 2*64*KST + 2*64*VST + 128*PST
#define ATTN_SMEM ((2 * 64 * KST + 2 * 64 * VST + 128 * PST) * 4)

__global__ __launch_bounds__(256) void attn_mma_kernel() {
    extern __shared__ float smf[];
    float* KsF0 = smf;                       // [64][KST]
    float* KsF1 = KsF0 + 64 * KST;
    float* VsF0 = KsF1 + 64 * KST;           // [64][VST]
    float* VsF1 = VsF0 + 64 * VST;
    uint32_t* Ps = reinterpret_cast<uint32_t*>(VsF1 + 64 * VST);  // [128][PST]

    const int qb = (gridDim.x - 1) - blockIdx.x;
    const int h = blockIdx.y;
    const int tid = threadIdx.x;
    const int w = tid >> 5;
    const int lane = tid & 31;
    const int g = lane >> 2;
    const int tg = lane & 3;
    const int r0g = qb * 128 + w * 16 + g;

    const uint32_t sK0 = smem_u32(KsF0), sK1 = smem_u32(KsF1);
    const uint32_t sV0 = smem_u32(VsF0), sV1 = smem_u32(VsF1);

    // Stage Q (scaled, tf32) into Ps, gather A-fragments.
    #pragma unroll 2
    for (int i = tid; i < 128 * 16; i += 256) {
        int r = i >> 4, cq = (i & 15) * 4;
        float4 v = *reinterpret_cast<const float4*>(
            &g_Q[(size_t)(qb * 128 + r) * DM + h * DK + cq]);
        uint32_t* p = &Ps[r * PST + cq];
        p[0] = f2tf32(v.x * 0.125f);
        p[1] = f2tf32(v.y * 0.125f);
        p[2] = f2tf32(v.z * 0.125f);
        p[3] = f2tf32(v.w * 0.125f);
    }
    __syncthreads();

    uint32_t qa[8][4];
    #pragma unroll
    for (int kc = 0; kc < 8; ++kc) {
        qa[kc][0] = Ps[(w * 16 + g) * PST + kc * 8 + tg];
        qa[kc][1] = Ps[(w * 16 + g + 8) * PST + kc * 8 + tg];
        qa[kc][2] = Ps[(w * 16 + g) * PST + kc * 8 + tg + 4];
        qa[kc][3] = Ps[(w * 16 + g + 8) * PST + kc * 8 + tg + 4];
    }

    // Per-thread KV load slots: 64x64 tile = 1024 float4 slots, 4 per thread.
    const int kvslot = tid * 4;

    auto load_kv = [&](int t, int st) {
        uint32_t sk = st ? sK1 : sK0;
        uint32_t sv = st ? sV1 : sV0;
        #pragma unroll
        for (int j = 0; j < 4; ++j) {
            int i = kvslot + j;
            int r = i >> 4, cq = (i & 15) * 4;
            size_t gk = (size_t)(t * 64 + r) * DM + h * DK + cq;
            cp_async16(sk + (r * KST + cq) * 4, &g_K[gk]);
            cp_async16(sv + (r * VST + cq) * 4, &g_V[gk]);
        }
        cp_commit();
    };

    float m0 = -1e30f, m1 = -1e30f, l0 = 0.0f, l1 = 0.0f;
    float o[8][4] = {};

    const int ntiles = 2 * qb + 2;
    load_kv(0, 0);

    for (int t = 0; t < ntiles; ++t) {
        const int st = t & 1;
        if (t + 1 < ntiles) {
            load_kv(t + 1, st ^ 1);
            cp_wait<1>();
        } else {
            cp_wait<0>();
        }
        __syncthreads();

        const float* Kf = st ? KsF1 : KsF0;
        const float* Vf = st ? VsF1 : VsF0;
        const bool warp_active = (t * 64 <= qb * 128 + w * 16 + 15);

        if (warp_active) {
            float sa[8][4] = {};
            #pragma unroll
            for (int kc = 0; kc < 8; ++kc) {
                uint32_t bf[8][2];
                #pragma unroll
                for (int nt = 0; nt < 8; ++nt) {
                    bf[nt][0] = f2tf32(Kf[(nt * 8 + g) * KST + kc * 8 + tg]);
                    bf[nt][1] = f2tf32(Kf[(nt * 8 + g) * KST + kc * 8 + tg + 4]);
                }
                #pragma unroll
                for (int nt = 0; nt < 8; ++nt)
                    mma_tf32(sa[nt], qa[kc], bf[nt]);
            }

            if (t >= 2 * qb) {
                #pragma unroll
                for (int nt = 0; nt < 8; ++nt) {
                    int c0 = t * 64 + nt * 8 + 2 * tg;
                    if (c0 > r0g)         sa[nt][0] = -1e30f;
                    if (c0 + 1 > r0g)     sa[nt][1] = -1e30f;
                    if (c0 > r0g + 8)     sa[nt][2] = -1e30f;
                    if (c0 + 1 > r0g + 8) sa[nt][3] = -1e30f;
                }
            }

            float smax0 = -1e30f, smax1 = -1e30f;
            #pragma unroll
            for (int nt = 0; nt < 8; ++nt) {
                smax0 = fmaxf(smax0, fmaxf(sa[nt][0], sa[nt][1]));
                smax1 = fmaxf(smax1, fmaxf(sa[nt][2], sa[nt][3]));
            }
            smax0 = fmaxf(smax0, __shfl_xor_sync(0xffffffffu, smax0, 1));
            smax0 = fmaxf(smax0, __shfl_xor_sync(0xffffffffu, smax0, 2));
            smax1 = fmaxf(smax1, __shfl_xor_sync(0xffffffffu, smax1, 1));
            smax1 = fmaxf(smax1, __shfl_xor_sync(0xffffffffu, smax1, 2));

            float mn0 = fmaxf(m0, smax0);
            float mn1 = fmaxf(m1, smax1);
            float corr0 = __expf(m0 - mn0);
            float corr1 = __expf(m1 - mn1);
            float rs0 = 0.0f, rs1 = 0.0f;
            #pragma unroll
            for (int nt = 0; nt < 8; ++nt) {
                sa[nt][0] = __expf(sa[nt][0] - mn0);
                sa[nt][1] = __expf(sa[nt][1] - mn0);
                sa[nt][2] = __expf(sa[nt][2] - mn1);
                sa[nt][3] = __expf(sa[nt][3] - mn1);
                rs0 += sa[nt][0] + sa[nt][1];
                rs1 += sa[nt][2] + sa[nt][3];
            }
            rs0 += __shfl_xor_sync(0xffffffffu, rs0, 1);
            rs0 += __shfl_xor_sync(0xffffffffu, rs0, 2);
            rs1 += __shfl_xor_sync(0xffffffffu, rs1, 1);
            rs1 += __shfl_xor_sync(0xffffffffu, rs1, 2);

            l0 = l0 * corr0 + rs0;  m0 = mn0;
            l1 = l1 * corr1 + rs1;  m1 = mn1;
            #pragma unroll
            for (int nt = 0; nt < 8; ++nt) {
                o[nt][0] *= corr0;  o[nt][1] *= corr0;
                o[nt][2] *= corr1;  o[nt][3] *= corr1;
            }

            #pragma unroll
            for (int nt = 0; nt < 8; ++nt) {
                int c = nt * 8 + 2 * tg;
                uint2 p0 = make_uint2(f2tf32(sa[nt][0]), f2tf32(sa[nt][1]));
                uint2 p1 = make_uint2(f2tf32(sa[nt][2]), f2tf32(sa[nt][3]));
                *reinterpret_cast<uint2*>(&Ps[(w * 16 + g) * PST + c]) = p0;
                *reinterpret_cast<uint2*>(&Ps[(w * 16 + g + 8) * PST + c]) = p1;
            }
        }
        __syncthreads();

        if (warp_active) {
            #pragma unroll
            for (int kc = 0; kc < 8; ++kc) {
                uint32_t pa[4];
                pa[0] = Ps[(w * 16 + g) * PST + kc * 8 + tg];
                pa[1] = Ps[(w * 16 + g + 8) * PST + kc * 8 + tg];
                pa[2] = Ps[(w * 16 + g) * PST + kc * 8 + tg + 4];
                pa[3] = Ps[(w * 16 + g + 8) * PST + kc * 8 + tg + 4];
                uint32_t bf[8][2];
                #pragma unroll
                for (int nt = 0; nt < 8; ++nt) {
                    bf[nt][0] = f2tf32(Vf[(kc * 8 + tg) * VST + nt * 8 + g]);
                    bf[nt][1] = f2tf32(Vf[(kc * 8 + tg + 4) * VST + nt * 8 + g]);
                }
                #pragma unroll
                for (int nt = 0; nt < 8; ++nt)
                    mma_tf32(o[nt], pa, bf[nt]);
            }
        }
        __syncthreads();   // all reads of buf st done before its re-fill at t+1
    }

    float inv0 = 1.0f / l0;
    float inv1 = 1.0f / l1;
    #pragma unroll
    for (int nt = 0; nt < 8; ++nt) {
        int col = h * DK + nt * 8 + 2 * tg;
        float2 v0 = make_float2(o[nt][0] * inv0, o[nt][1] * inv0);
        float2 v1 = make_float2(o[nt][2] * inv1, o[nt][3] * inv1);
        *reinterpret_cast<float2*>(&g_C[(size_t)r0g * DM + col]) = v0;
        *reinterpret_cast<float2*>(&g_C[(size_t)(r0g + 8) * DM + col]) = v1;
    }
}

// ---------------------------------------------------------------------------
// Launch
// ---------------------------------------------------------------------------
extern "C" void kernel_launch(void* const* d_in, const int* in_sizes, int n_in,
                              void* d_out, int out_size) {
    const float* q  = (const float*)d_in[0];
    const float* k  = (const float*)d_in[1];
    const float* v  = (const float*)d_in[2];
    // d_in[3] = mask (tril, enforced analytically)
    const float* Wq = (const float*)d_in[4];
    const float* bq = (const float*)d_in[5];
    const float* Wk = (const float*)d_in[6];
    const float* bk = (const float*)d_in[7];
    const float* Wv = (const float*)d_in[8];
    const float* bv = (const float*)d_in[9];
    const float* Wo = (const float*)d_in[10];
    const float* bo = (const float*)d_in[11];
    float* out = (float*)d_out;

    const int S = in_sizes[0] / DM;   // 4096

    float *pQ, *pK, *pV, *pC;
    cudaGetSymbolAddress((void**)&pQ, g_Q);
    cudaGetSymbolAddress((void**)&pK, g_K);
    cudaGetSymbolAddress((void**)&pV, g_V);
    cudaGetSymbolAddress((void**)&pC, g_C);

    dim3 qkvgrid(DM / BN, S / BM, 3);   // (6, 32, 3)
    gemm_qkv_kernel<<<qkvgrid, 256>>>(q, k, v, Wq, Wk, Wv, bq, bk, bv, pQ, pK, pV);

    cudaFuncSetAttribute(attn_mma_kernel,
                         cudaFuncAttributeMaxDynamicSharedMemorySize, ATTN_SMEM);
    attn_mma_kernel<<<dim3(S / 128, NH), 256, ATTN_SMEM>>>();

    dim3 ggrid(DM / BN, S / BM);
    gemm_single_kernel<<<ggrid, 256>>>(pC, Wo, bo, out);
}